// round 2
// baseline (speedup 1.0000x reference)
#include <cuda_runtime.h>
#include <cstdint>

// MaxUnpooling2D, fixed shapes:
//   updates [16,64,64,256] f32, mask [16,64,64,256] i32
//   out     [16,128,128,256] f32   (oH=oW=128, C=256)
// mask = (y*128 + x)*256 + c  with y = 2h+dy, x = 2w+dx, dy,dx in {0,1}.
// Gather/demux formulation: one thread per (b,h,w,c4) group of 4 channels
// reads its update+mask once and writes all 4 window slots (3 zeros + hit).
// Every output element is written exactly once -> no zero pass, no atomics.
//
// Slot decode: dy = (m>>15)&1, dx = (m>>8)&1  (parity bits of y and x),
// so k = dy*2+dx = ((m>>14)&2) | ((m>>8)&1).

__global__ void __launch_bounds__(256, 8)
maxunpool_kernel(const float4* __restrict__ upd,
                 const int4*  __restrict__ mask,
                 float4*      __restrict__ out)
{
    unsigned i = blockIdx.x * blockDim.x + threadIdx.x;  // < 2^22 exactly

    float4 u = upd[i];
    int4   m = mask[i];

    int k0 = ((m.x >> 14) & 2) | ((m.x >> 8) & 1);
    int k1 = ((m.y >> 14) & 2) | ((m.y >> 8) & 1);
    int k2 = ((m.z >> 14) & 2) | ((m.z >> 8) & 1);
    int k3 = ((m.w >> 14) & 2) | ((m.w >> 8) & 1);

    // i = b<<18 | h<<12 | w<<6 | c4   (b<16, h,w,c4 < 64)
    // out float4 base = b<<20 | (2h)<<13 | (2w)<<6 | c4
    //                 = b<<20 | h<<14 | w<<7 | c4
    unsigned base = ( i         & 63u)
                  | ((i >>  6) & 63u) << 7
                  | ((i >> 12) & 63u) << 14
                  | ( i >> 18)        << 20;

    // dy stride = 128*64 = 8192 float4s (1<<13); dx stride = 64 (1<<6).
    #pragma unroll
    for (int k = 0; k < 4; k++) {
        float4 o;
        o.x = (k0 == k) ? u.x : 0.0f;
        o.y = (k1 == k) ? u.y : 0.0f;
        o.z = (k2 == k) ? u.z : 0.0f;
        o.w = (k3 == k) ? u.w : 0.0f;
        unsigned off = base + ((unsigned)(k >> 1) << 13) + ((unsigned)(k & 1) << 6);
        out[off] = o;
    }
}

extern "C" void kernel_launch(void* const* d_in, const int* in_sizes, int n_in,
                              void* d_out, int out_size)
{
    const float4* upd  = (const float4*)d_in[0];
    const int4*   mask = (const int4*)d_in[1];
    float4*       out  = (float4*)d_out;

    // total threads = 16*64*64*(256/4) = 4,194,304
    const int total = 16 * 64 * 64 * 64;
    const int tpb = 256;
    maxunpool_kernel<<<total / tpb, tpb>>>(upd, mask, out);
}